// round 4
// baseline (speedup 1.0000x reference)
#include <cuda_runtime.h>
#include <math.h>

// Shapes (fixed by the benchmark's setup_inputs):
//   in_H  [NI=16,1]   out_H [NO=16,1]
//   weight_H [O=512, CIN=512, K=16]
//   weight   [O=512, 1, KS=7, KS=7]
//   grid_H [16,1] (unused: uniform grid is implied by K)
//   grid_Rn [7,7,2]   mask [7,7]
// Output = concat( weight_H_out [512,16,512,16] , w [512,16,1,7,7] ) as f32.

#define TWO_PI_F 6.2831853071795864769f

static const int O_   = 512;
static const int CIN_ = 512;
static const int K_   = 16;
static const int NI_  = 16;
static const int NO_  = 16;
static const int KS_  = 7;

static const long long OUT1_ELEMS = (long long)O_ * NI_ * CIN_ * NO_;   // 67108864
static const int       OUT2_ELEMS = O_ * NO_ * KS_ * KS_;               // 401408

// ---------------------------------------------------------------------------
// Kernel 1: weight_H_out[o,ni,c,no] = (1-f)*W[o,c,i0] + f*W[o,c,i1]
// One thread produces 4 consecutive `no` outputs -> one float4 store.
// 256-entry (frac, i0) pair table computed per block into shared memory.
// ---------------------------------------------------------------------------
__global__ void __launch_bounds__(256)
lerp_kernel(const float* __restrict__ in_H,
            const float* __restrict__ out_H,
            const float* __restrict__ weight_H,
            float* __restrict__ out)
{
    __shared__ float s_frac[256];
    __shared__ int   s_i0[256];

    {
        int p  = threadIdx.x;            // 256 threads = 256 (ni,no) pairs
        int ni = p >> 4;
        int no = p & 15;
        float a = in_H[ni] - out_H[no];
        float m = fmodf(a, TWO_PI_F);
        if (m < 0.0f) m += TWO_PI_F;     // jnp.mod semantics: result in [0, 2pi)
        float t   = m * ((float)K_ / TWO_PI_F);
        float i0f = floorf(t);
        s_frac[p] = t - i0f;
        s_i0[p]   = ((int)i0f) & (K_ - 1);
    }
    __syncthreads();

    unsigned int tid = blockIdx.x * blockDim.x + threadIdx.x;  // 0 .. 16777215
    // Output element index = tid*4. Decompose (no fastest):
    int no_q = (int)(tid & 3);           // which group of 4 no's
    int c    = (int)((tid >> 2) & 511);
    int ni   = (int)((tid >> 11) & 15);
    int o    = (int)(tid >> 15);

    const float* wrow = weight_H + (((size_t)o << 9) + (size_t)c) * (size_t)K_;

    float r[4];
    #pragma unroll
    for (int j = 0; j < 4; ++j) {
        int pp = (ni << 4) + (no_q << 2) + j;
        float f = s_frac[pp];
        int k0  = s_i0[pp];
        int k1  = (k0 + 1) & (K_ - 1);
        float a = __ldg(wrow + k0);
        float b = __ldg(wrow + k1);
        r[j] = (1.0f - f) * a + f * b;
    }
    float4 v = make_float4(r[0], r[1], r[2], r[3]);
    reinterpret_cast<float4*>(out)[tid] = v;
}

// ---------------------------------------------------------------------------
// Kernel 2: w[o,no,0,h,w] = mask[h,w] * bilinear(weight[o], R(-out_H[no]) @ grid_Rn[h,w])
// One thread per output element; tiny workload.
// ---------------------------------------------------------------------------
__device__ __forceinline__ float gather7(const float* __restrict__ img, int yy, int xx)
{
    if (yy < 0 || yy > (KS_ - 1) || xx < 0 || xx > (KS_ - 1)) return 0.0f;
    return img[yy * KS_ + xx];
}

__global__ void __launch_bounds__(256)
rot_kernel(const float* __restrict__ out_H,
           const float* __restrict__ weight,
           const float* __restrict__ grid_Rn,
           const float* __restrict__ mask,
           float* __restrict__ out)
{
    int tid = blockIdx.x * blockDim.x + threadIdx.x;
    if (tid >= OUT2_ELEMS) return;

    int kx = tid % KS_;
    int ky = (tid / KS_) % KS_;
    int no = (tid / (KS_ * KS_)) & (NO_ - 1);
    int o  = tid / (NO_ * KS_ * KS_);

    // angle = -out_H[no]; R = [[c,-s],[s,c]]
    double a  = -(double)out_H[no];
    float  ca = (float)cos(a);
    float  sa = (float)sin(a);

    float gx = grid_Rn[(ky * KS_ + kx) * 2 + 0];
    float gy = grid_Rn[(ky * KS_ + kx) * 2 + 1];

    float xr = ca * gx - sa * gy;
    float yr = sa * gx + ca * gy;

    // map [-1,1] -> [0, KS-1]
    float x = (xr + 1.0f) * 0.5f * (float)(KS_ - 1);
    float y = (yr + 1.0f) * 0.5f * (float)(KS_ - 1);

    float x0f = floorf(x), y0f = floorf(y);
    float wx = x - x0f,  wy = y - y0f;
    int   x0 = (int)x0f, y0 = (int)y0f;

    const float* img = weight + (size_t)o * (KS_ * KS_);

    float v = (1.0f - wy) * (1.0f - wx) * gather7(img, y0,     x0)
            + (1.0f - wy) * wx          * gather7(img, y0,     x0 + 1)
            + wy          * (1.0f - wx) * gather7(img, y0 + 1, x0)
            + wy          * wx          * gather7(img, y0 + 1, x0 + 1);

    out[tid] = mask[ky * KS_ + kx] * v;
}

// ---------------------------------------------------------------------------
// Launch
// ---------------------------------------------------------------------------
extern "C" void kernel_launch(void* const* d_in, const int* in_sizes, int n_in,
                              void* d_out, int out_size)
{
    const float* in_H     = (const float*)d_in[0];
    const float* out_H    = (const float*)d_in[1];
    const float* weight_H = (const float*)d_in[2];
    const float* weight   = (const float*)d_in[3];
    /* d_in[4] = grid_H (uniform circular grid, implied) */
    const float* grid_Rn  = (const float*)d_in[5];
    const float* mask     = (const float*)d_in[6];

    float* out = (float*)d_out;

    // Kernel 1: 67108864 outputs / 4 per thread = 16777216 threads
    const unsigned int n_thr1 = (unsigned int)(OUT1_ELEMS / 4);
    lerp_kernel<<<n_thr1 / 256, 256>>>(in_H, out_H, weight_H, out);

    // Kernel 2: 401408 outputs
    rot_kernel<<<(OUT2_ELEMS + 255) / 256, 256>>>(out_H, weight, grid_Rn, mask,
                                                  out + OUT1_ELEMS);
}

// round 5
// speedup vs baseline: 1.6883x; 1.6883x over previous
#include <cuda_runtime.h>
#include <math.h>

// Shapes (fixed): in_H[16,1] out_H[16,1] weight_H[512,512,16] weight[512,1,7,7]
// grid_H[16,1] (implied uniform) grid_Rn[7,7,2] mask[7,7]
// Output = concat( weight_H_out [512,16,512,16] , w [512,16,1,7,7] ) as f32.

#define TWO_PI_F 6.2831853071795864769f

static const int O_   = 512;
static const int CIN_ = 512;
static const int K_   = 16;
static const int NI_  = 16;
static const int NO_  = 16;
static const int KS_  = 7;

static const long long OUT1_ELEMS = (long long)O_ * NI_ * CIN_ * NO_;   // 67108864
static const int       OUT2_ELEMS = O_ * NO_ * KS_ * KS_;               // 401408

// Lerp part: block = (o, 64-row c-chunk). 512 o * 8 chunks = 4096 blocks.
static const int LERP_BLOCKS = O_ * (CIN_ / 64);                        // 4096
static const int ROT_BLOCKS  = OUT2_ELEMS / 256;                        // 1568
static const int ROW_PAD     = 17;   // smem row stride (floats), odd -> conflict-lean

__device__ __forceinline__ float gather7(const float* __restrict__ img, int yy, int xx)
{
    if (yy < 0 || yy > (KS_ - 1) || xx < 0 || xx > (KS_ - 1)) return 0.0f;
    return img[yy * KS_ + xx];
}

__global__ void __launch_bounds__(256)
fused_kernel(const float* __restrict__ in_H,
             const float* __restrict__ out_H,
             const float* __restrict__ weight_H,
             const float* __restrict__ weight,
             const float* __restrict__ grid_Rn,
             const float* __restrict__ mask,
             float* __restrict__ out)
{
    if (blockIdx.x < (unsigned)LERP_BLOCKS) {
        // ============== Part 1: circular-lerp broadcast (HBM-bound) ==============
        __shared__ float  s_w[64 * ROW_PAD];   // 64 W-rows of 16 floats, padded
        __shared__ float2 s_tab[256];          // (frac, bitcast(k0)) per (ni,no) pair

        const int b  = blockIdx.x;
        const int o  = b >> 3;
        const int c0 = (b & 7) * 64;
        const int t  = threadIdx.x;

        // Phase 1a: pair table (256 threads = 256 (ni,no) pairs)
        {
            int ni = t >> 4;
            int no = t & 15;
            float a = in_H[ni] - out_H[no];
            float m = fmodf(a, TWO_PI_F);
            if (m < 0.0f) m += TWO_PI_F;              // jnp.mod: result in [0, 2pi)
            float tt  = m * ((float)K_ / TWO_PI_F);
            float i0f = floorf(tt);
            int   k0  = ((int)i0f) & (K_ - 1);
            s_tab[t]  = make_float2(tt - i0f, __int_as_float(k0));
        }

        // Phase 1b: stage 64 W-rows (4 KB contiguous) into padded smem.
        // thread t loads float4 #t of the chunk: row = t>>2, quad = t&3.
        {
            const float4 v = reinterpret_cast<const float4*>(
                weight_H + ((size_t)o * CIN_ + c0) * K_)[t];
            float* dst = s_w + (t >> 2) * ROW_PAD + (t & 3) * 4;
            dst[0] = v.x; dst[1] = v.y; dst[2] = v.z; dst[3] = v.w;
        }
        __syncthreads();

        // Phase 2: each thread owns (c_local, no_q); loops ni; 1 float4 store each.
        const int c_local = t >> 2;
        const int no_q    = t & 3;
        const int c       = c0 + c_local;
        const float* __restrict__ wr = s_w + c_local * ROW_PAD;

        // out[((o*16+ni)*512 + c)*16 + no_q*4], as float4 index:
        size_t f4_base = ((((size_t)o * NI_) * CIN_ + c) * NO_ + no_q * 4) >> 2;
        const size_t f4_stride = (size_t)(CIN_ * NO_) >> 2;   // per-ni step = 2048

        float4* __restrict__ out4 = reinterpret_cast<float4*>(out);

        #pragma unroll 4
        for (int ni = 0; ni < NI_; ++ni) {
            float r[4];
            #pragma unroll
            for (int j = 0; j < 4; ++j) {
                float2 tb = s_tab[ni * 16 + no_q * 4 + j];
                float f   = tb.x;
                int   k0  = __float_as_int(tb.y);
                int   k1  = (k0 + 1) & (K_ - 1);
                float w0  = wr[k0];
                float w1  = wr[k1];
                r[j] = w0 + f * (w1 - w0);
            }
            out4[f4_base + (size_t)ni * f4_stride] = make_float4(r[0], r[1], r[2], r[3]);
        }
    } else {
        // ============== Part 2: rotated bilinear resample (tiny) ==============
        int tid = (blockIdx.x - LERP_BLOCKS) * 256 + threadIdx.x;

        int kx = tid % KS_;
        int ky = (tid / KS_) % KS_;
        int no = (tid / (KS_ * KS_)) & (NO_ - 1);
        int o  = tid / (NO_ * KS_ * KS_);

        float ca, sa;
        sincosf(-out_H[no], &sa, &ca);    // angle = -out_H[no]

        float gx = grid_Rn[(ky * KS_ + kx) * 2 + 0];
        float gy = grid_Rn[(ky * KS_ + kx) * 2 + 1];

        float xr = ca * gx - sa * gy;
        float yr = sa * gx + ca * gy;

        float x = (xr + 1.0f) * 0.5f * (float)(KS_ - 1);
        float y = (yr + 1.0f) * 0.5f * (float)(KS_ - 1);

        float x0f = floorf(x), y0f = floorf(y);
        float wx = x - x0f,  wy = y - y0f;
        int   x0 = (int)x0f, y0 = (int)y0f;

        const float* img = weight + (size_t)o * (KS_ * KS_);

        float v = (1.0f - wy) * (1.0f - wx) * gather7(img, y0,     x0)
                + (1.0f - wy) * wx          * gather7(img, y0,     x0 + 1)
                + wy          * (1.0f - wx) * gather7(img, y0 + 1, x0)
                + wy          * wx          * gather7(img, y0 + 1, x0 + 1);

        out[OUT1_ELEMS + tid] = mask[ky * KS_ + kx] * v;
    }
}

extern "C" void kernel_launch(void* const* d_in, const int* in_sizes, int n_in,
                              void* d_out, int out_size)
{
    const float* in_H     = (const float*)d_in[0];
    const float* out_H    = (const float*)d_in[1];
    const float* weight_H = (const float*)d_in[2];
    const float* weight   = (const float*)d_in[3];
    /* d_in[4] = grid_H (uniform circular grid, implied by K) */
    const float* grid_Rn  = (const float*)d_in[5];
    const float* mask     = (const float*)d_in[6];

    fused_kernel<<<LERP_BLOCKS + ROT_BLOCKS, 256>>>(
        in_H, out_H, weight_H, weight, grid_Rn, mask, (float*)d_out);
}

// round 6
// speedup vs baseline: 1.7419x; 1.0318x over previous
#include <cuda_runtime.h>
#include <math.h>

// Shapes (fixed): in_H[16,1] out_H[16,1] weight_H[512,512,16] weight[512,1,7,7]
// grid_H[16,1] (implied uniform) grid_Rn[7,7,2] mask[7,7]
// Output = concat( weight_H_out [512,16,512,16] , w [512,16,1,7,7] ) as f32.

#define TWO_PI_F 6.2831853071795864769f

static const int O_   = 512;
static const int CIN_ = 512;
static const int K_   = 16;
static const int NI_  = 16;
static const int NO_  = 16;
static const int KS_  = 7;

static const long long OUT1_ELEMS = (long long)O_ * NI_ * CIN_ * NO_;   // 67108864
static const int       OUT2_ELEMS = O_ * NO_ * KS_ * KS_;               // 401408

static const int LERP_BLOCKS = O_ * (CIN_ / 64);                        // 4096
static const int ROT_BLOCKS  = OUT2_ELEMS / 256;                        // 1568
static const int PSTRIDE     = 17;   // float2 units per smem row (16 + 1 pad)

__device__ __forceinline__ float gather7(const float* __restrict__ img, int yy, int xx)
{
    if (yy < 0 || yy > (KS_ - 1) || xx < 0 || xx > (KS_ - 1)) return 0.0f;
    return img[yy * KS_ + xx];
}

__global__ void __launch_bounds__(256)
fused_kernel(const float* __restrict__ in_H,
             const float* __restrict__ out_H,
             const float* __restrict__ weight_H,
             const float* __restrict__ weight,
             const float* __restrict__ grid_Rn,
             const float* __restrict__ mask,
             float* __restrict__ out)
{
    if (blockIdx.x < (unsigned)LERP_BLOCKS) {
        // ============== Part 1: circular-lerp broadcast ==============
        // s_wp[c][k] holds the duplicated tap pair (W[k], W[(k+1)&15]) -> 1 LDS.64/tap.
        __shared__ float2 s_wp[64 * PSTRIDE];
        __shared__ float4 s_frac4[64];   // fracs for (ni, no_q): 4 consecutive no
        __shared__ unsigned s_idx[64];   // 4 packed k0 bytes for (ni, no_q)

        const int b  = blockIdx.x;
        const int o  = b >> 3;
        const int c0 = (b & 7) * 64;
        const int t  = threadIdx.x;

        // Phase 1a: pair tables. 64 threads each compute a (ni, no_q) group of 4.
        if (t < 64) {
            int ni   = t >> 2;
            int no_q = t & 3;
            float fin = in_H[ni];
            float fr[4];
            unsigned idx = 0;
            #pragma unroll
            for (int j = 0; j < 4; ++j) {
                int no = no_q * 4 + j;
                float a = fin - out_H[no];
                float m = fmodf(a, TWO_PI_F);
                if (m < 0.0f) m += TWO_PI_F;          // jnp.mod: [0, 2pi)
                float tt  = m * ((float)K_ / TWO_PI_F);
                float i0f = floorf(tt);
                fr[j]     = tt - i0f;
                idx |= (unsigned)(((int)i0f) & (K_ - 1)) << (8 * j);
            }
            s_frac4[t] = make_float4(fr[0], fr[1], fr[2], fr[3]);
            s_idx[t]   = idx;
        }

        // Phase 1b: stage 64 W-rows as duplicated float2 pairs.
        // Thread t loads float4 #t of the 4KB chunk: row = t>>2, quad q = t&3,
        // covering taps k = 4q..4q+3. The (k=4q+3) pair needs the next quad's .x,
        // fetched via shfl from the lane owning quad (q+1)&3 of the same row.
        {
            const float4 v = reinterpret_cast<const float4*>(
                weight_H + ((size_t)o * CIN_ + c0) * K_)[t];
            const int row  = t >> 2;
            const int q    = t & 3;
            const int lane = t & 31;
            const int src  = (lane & ~3) | ((q + 1) & 3);
            const float nxt = __shfl_sync(0xffffffffu, v.x, src);

            float2* dst = s_wp + row * PSTRIDE + q * 4;
            dst[0] = make_float2(v.x, v.y);
            dst[1] = make_float2(v.y, v.z);
            dst[2] = make_float2(v.z, v.w);
            dst[3] = make_float2(v.w, nxt);
        }
        __syncthreads();

        // Phase 2: thread owns (c_local, no_q); loops ni; 1 float4 store each.
        const int c_local = t >> 2;
        const int no_q    = t & 3;
        const int c       = c0 + c_local;
        const float2* __restrict__ wp = s_wp + c_local * PSTRIDE;

        size_t f4_base = ((((size_t)o * NI_) * CIN_ + c) * NO_ + no_q * 4) >> 2;
        const size_t f4_stride = (size_t)(CIN_ * NO_) >> 2;   // per-ni step

        float4* __restrict__ out4 = reinterpret_cast<float4*>(out);

        #pragma unroll
        for (int ni = 0; ni < NI_; ++ni) {
            const int g = (ni << 2) | no_q;
            const float4   f4  = s_frac4[g];
            const unsigned idx = s_idx[g];

            float2 t0 = wp[(idx      ) & 15];
            float2 t1 = wp[(idx >>  8) & 15];
            float2 t2 = wp[(idx >> 16) & 15];
            float2 t3 = wp[(idx >> 24) & 15];

            float4 r;
            r.x = t0.x + f4.x * (t0.y - t0.x);
            r.y = t1.x + f4.y * (t1.y - t1.x);
            r.z = t2.x + f4.z * (t2.y - t2.x);
            r.w = t3.x + f4.w * (t3.y - t3.x);

            out4[f4_base + (size_t)ni * f4_stride] = r;
        }
    } else {
        // ============== Part 2: rotated bilinear resample (tiny) ==============
        int tid = (blockIdx.x - LERP_BLOCKS) * 256 + threadIdx.x;

        int kx = tid % KS_;
        int ky = (tid / KS_) % KS_;
        int no = (tid / (KS_ * KS_)) & (NO_ - 1);
        int o  = tid / (NO_ * KS_ * KS_);

        float ca, sa;
        sincosf(-out_H[no], &sa, &ca);    // angle = -out_H[no]

        float gx = grid_Rn[(ky * KS_ + kx) * 2 + 0];
        float gy = grid_Rn[(ky * KS_ + kx) * 2 + 1];

        float xr = ca * gx - sa * gy;
        float yr = sa * gx + ca * gy;

        float x = (xr + 1.0f) * 0.5f * (float)(KS_ - 1);
        float y = (yr + 1.0f) * 0.5f * (float)(KS_ - 1);

        float x0f = floorf(x), y0f = floorf(y);
        float wx = x - x0f,  wy = y - y0f;
        int   x0 = (int)x0f, y0 = (int)y0f;

        const float* img = weight + (size_t)o * (KS_ * KS_);

        float v = (1.0f - wy) * (1.0f - wx) * gather7(img, y0,     x0)
                + (1.0f - wy) * wx          * gather7(img, y0,     x0 + 1)
                + wy          * (1.0f - wx) * gather7(img, y0 + 1, x0)
                + wy          * wx          * gather7(img, y0 + 1, x0 + 1);

        out[OUT1_ELEMS + tid] = mask[ky * KS_ + kx] * v;
    }
}

extern "C" void kernel_launch(void* const* d_in, const int* in_sizes, int n_in,
                              void* d_out, int out_size)
{
    const float* in_H     = (const float*)d_in[0];
    const float* out_H    = (const float*)d_in[1];
    const float* weight_H = (const float*)d_in[2];
    const float* weight   = (const float*)d_in[3];
    /* d_in[4] = grid_H (uniform circular grid, implied by K) */
    const float* grid_Rn  = (const float*)d_in[5];
    const float* mask     = (const float*)d_in[6];

    fused_kernel<<<LERP_BLOCKS + ROT_BLOCKS, 256>>>(
        in_H, out_H, weight_H, weight, grid_Rn, mask, (float*)d_out);
}

// round 7
// speedup vs baseline: 1.8218x; 1.0459x over previous
#include <cuda_runtime.h>
#include <math.h>

// Shapes (fixed): in_H[16,1] out_H[16,1] weight_H[512,512,16] weight[512,1,7,7]
// grid_H[16,1] (implied uniform) grid_Rn[7,7,2] mask[7,7]
// Output = concat( weight_H_out [512,16,512,16] , w [512,16,1,7,7] ) as f32.

#define TWO_PI_F 6.2831853071795864769f

static const int O_   = 512;
static const int CIN_ = 512;
static const int K_   = 16;
static const int NI_  = 16;
static const int NO_  = 16;
static const int KS_  = 7;

static const long long OUT1_ELEMS = (long long)O_ * NI_ * CIN_ * NO_;   // 67108864
static const int       OUT2_ELEMS = O_ * NO_ * KS_ * KS_;               // 401408

// Part 1: block = (o, 128-row c-chunk). 512 o * 4 chunks = 2048 blocks.
// 8 warps/block, warp owns 2 adjacent c-rows per sweep, 8 sweeps of 16 rows.
static const int CHUNK_C     = 128;
static const int LERP_BLOCKS = O_ * (CIN_ / CHUNK_C);                   // 2048
static const int ROT_BLOCKS  = OUT2_ELEMS / 256;                       // 1568

__device__ __forceinline__ float gather7(const float* __restrict__ img, int yy, int xx)
{
    if (yy < 0 || yy > (KS_ - 1) || xx < 0 || xx > (KS_ - 1)) return 0.0f;
    return img[yy * KS_ + xx];
}

__global__ void __launch_bounds__(256)
fused_kernel(const float* __restrict__ in_H,
             const float* __restrict__ out_H,
             const float* __restrict__ weight_H,
             const float* __restrict__ weight,
             const float* __restrict__ grid_Rn,
             const float* __restrict__ mask,
             float* __restrict__ out)
{
    if (blockIdx.x < (unsigned)LERP_BLOCKS) {
        // ============== Part 1: circular-lerp broadcast (register/shfl version) ==============
        const int b      = blockIdx.x;
        const int o      = b >> 2;
        const int c_base = (b & 3) * CHUNK_C;
        const int t      = threadIdx.x;
        const int warp   = t >> 5;
        const int lane   = t & 31;
        const int no     = lane & 15;     // lane's fixed output-angle index
        const int hsel   = lane & 16;     // shfl half-selector (row 0 vs row 1)

        // Per-lane setup: 16 fracs (registers) + 16 packed 4-bit k0's.
        float frac[NI_];
        unsigned klo = 0, khi = 0;
        {
            const float oh = __ldg(out_H + no);
            #pragma unroll
            for (int ni = 0; ni < NI_; ++ni) {
                float a = __ldg(in_H + ni) - oh;
                float m = fmodf(a, TWO_PI_F);
                if (m < 0.0f) m += TWO_PI_F;          // jnp.mod: [0, 2pi)
                float tt  = m * ((float)K_ / TWO_PI_F);
                float i0f = floorf(tt);
                frac[ni]  = tt - i0f;
                unsigned k0 = ((unsigned)(int)i0f) & (K_ - 1);
                if (ni < 8) klo |= k0 << (4 * ni);
                else        khi |= k0 << (4 * (ni - 8));
            }
        }

        // Sweep 8 row-pairs: warp w handles rows (c_base + s*16 + w*2 + half).
        #pragma unroll 1
        for (int s = 0; s < 8; ++s) {
            const int row = c_base + s * 16 + warp * 2 + (lane >> 4);

            // Lane holds tap k = lane&15 of its row. 32 lanes = two adjacent
            // 64B rows = one 128B coalesced LDG.
            const float tap = __ldg(weight_H + (((size_t)o << 9) + row) * K_ + no);

            // out[((o*16+ni)*512 + row)*16 + no]; per-ni stride = 8192 floats.
            float* __restrict__ p = out + (((size_t)o * NI_ * CIN_) + row) * NO_ + no;

            #pragma unroll
            for (int ni = 0; ni < NI_; ++ni) {
                const unsigned pk = (ni < 8) ? klo : khi;
                const unsigned k0 = (pk >> (4 * (ni & 7))) & 15u;
                const unsigned k1 = (k0 + 1) & 15u;
                const float w0 = __shfl_sync(0xffffffffu, tap, (int)(hsel | k0));
                const float w1 = __shfl_sync(0xffffffffu, tap, (int)(hsel | k1));
                p[(size_t)ni * (CIN_ * NO_)] = w0 + frac[ni] * (w1 - w0);
            }
        }
    } else {
        // ============== Part 2: rotated bilinear resample (tiny) ==============
        int tid = (blockIdx.x - LERP_BLOCKS) * 256 + threadIdx.x;

        int kx = tid % KS_;
        int ky = (tid / KS_) % KS_;
        int no = (tid / (KS_ * KS_)) & (NO_ - 1);
        int o  = tid / (NO_ * KS_ * KS_);

        float ca, sa;
        sincosf(-out_H[no], &sa, &ca);    // angle = -out_H[no]

        float gx = grid_Rn[(ky * KS_ + kx) * 2 + 0];
        float gy = grid_Rn[(ky * KS_ + kx) * 2 + 1];

        float xr = ca * gx - sa * gy;
        float yr = sa * gx + ca * gy;

        float x = (xr + 1.0f) * 0.5f * (float)(KS_ - 1);
        float y = (yr + 1.0f) * 0.5f * (float)(KS_ - 1);

        float x0f = floorf(x), y0f = floorf(y);
        float wx = x - x0f,  wy = y - y0f;
        int   x0 = (int)x0f, y0 = (int)y0f;

        const float* img = weight + (size_t)o * (KS_ * KS_);

        float v = (1.0f - wy) * (1.0f - wx) * gather7(img, y0,     x0)
                + (1.0f - wy) * wx          * gather7(img, y0,     x0 + 1)
                + wy          * (1.0f - wx) * gather7(img, y0 + 1, x0)
                + wy          * wx          * gather7(img, y0 + 1, x0 + 1);

        out[OUT1_ELEMS + tid] = mask[ky * KS_ + kx] * v;
    }
}

extern "C" void kernel_launch(void* const* d_in, const int* in_sizes, int n_in,
                              void* d_out, int out_size)
{
    const float* in_H     = (const float*)d_in[0];
    const float* out_H    = (const float*)d_in[1];
    const float* weight_H = (const float*)d_in[2];
    const float* weight   = (const float*)d_in[3];
    /* d_in[4] = grid_H (uniform circular grid, implied by K) */
    const float* grid_Rn  = (const float*)d_in[5];
    const float* mask     = (const float*)d_in[6];

    fused_kernel<<<LERP_BLOCKS + ROT_BLOCKS, 256>>>(
        in_H, out_H, weight_H, weight, grid_Rn, mask, (float*)d_out);
}

// round 8
// speedup vs baseline: 2.1750x; 1.1938x over previous
#include <cuda_runtime.h>
#include <math.h>

// Shapes (fixed): in_H[16,1] out_H[16,1] weight_H[512,512,16] weight[512,1,7,7]
// grid_H[16,1] (implied uniform) grid_Rn[7,7,2] mask[7,7]
// Output = concat( weight_H_out [512,16,512,16] , w [512,16,1,7,7] ) as f32.

#define TWO_PI_F 6.2831853071795864769f

static const int O_   = 512;
static const int CIN_ = 512;
static const int K_   = 16;
static const int NI_  = 16;
static const int NO_  = 16;
static const int KS_  = 7;

static const long long OUT1_ELEMS = (long long)O_ * NI_ * CIN_ * NO_;   // 67108864
static const int       OUT2_ELEMS = O_ * NO_ * KS_ * KS_;               // 401408

// Part 1: block = (o, 128-row c-chunk). 512 o * 4 chunks = 2048 blocks.
// 8 warps/block; warp covers rows {warp*2 + half + s*16 : s=0..7} of its chunk.
static const int CHUNK_C     = 128;
static const int LERP_BLOCKS = O_ * (CIN_ / CHUNK_C);                   // 2048
static const int ROT_BLOCKS  = OUT2_ELEMS / 256;                        // 1568

__device__ __forceinline__ float gather7(const float* __restrict__ img, int yy, int xx)
{
    if (yy < 0 || yy > (KS_ - 1) || xx < 0 || xx > (KS_ - 1)) return 0.0f;
    return img[yy * KS_ + xx];
}

__global__ void __launch_bounds__(256)
fused_kernel(const float* __restrict__ in_H,
             const float* __restrict__ out_H,
             const float* __restrict__ weight_H,
             const float* __restrict__ weight,
             const float* __restrict__ grid_Rn,
             const float* __restrict__ mask,
             float* __restrict__ out)
{
    if (blockIdx.x < (unsigned)LERP_BLOCKS) {
        // ============== Part 1: circular-lerp broadcast ==============
        __shared__ float2 s_tab[256];   // (frac, bitcast(k0)) per (ni,no) pair

        const int b      = blockIdx.x;
        const int o      = b >> 2;
        const int c_base = (b & 3) * CHUNK_C;
        const int t      = threadIdx.x;
        const int warp   = t >> 5;
        const int lane   = t & 31;
        const int no     = lane & 15;     // lane's output-angle index == tap slot
        const int hsel   = lane & 16;     // shfl half-selector (row 0 vs row 1)

        // Pair table: 256 threads = 256 (ni,no) pairs.
        {
            int ni = t >> 4;
            int po = t & 15;
            float a = in_H[ni] - out_H[po];
            float m = fmodf(a, TWO_PI_F);
            if (m < 0.0f) m += TWO_PI_F;              // jnp.mod: [0, 2pi)
            float tt  = m * ((float)K_ / TWO_PI_F);
            float i0f = floorf(tt);
            int   k0  = ((int)i0f) & (K_ - 1);
            s_tab[t]  = make_float2(tt - i0f, __int_as_float(k0));
        }
        __syncthreads();

        // Load all 8 taps up front. Per s: 32 lanes read two adjacent 64B
        // rows = one 128B coalesced LDG. Lane holds tap k=no of its row.
        const int row0 = c_base + warp * 2 + (lane >> 4);
        float tap[8];
        #pragma unroll
        for (int s = 0; s < 8; ++s)
            tap[s] = __ldg(weight_H + (((size_t)o << 9) + (row0 + s * 16)) * K_ + no);

        // out[o*131072 + ni*8192 + row*16 + no]; row step per s = 16 -> 256 floats.
        float* __restrict__ base =
            out + ((size_t)o << 17) + ((size_t)row0 << 4) + no;

        #pragma unroll
        for (int ni = 0; ni < NI_; ++ni) {
            const float2 tb = s_tab[(ni << 4) | no];
            const int k0 = __float_as_int(tb.y);
            const int s0 = hsel | k0;
            const int s1 = hsel | ((k0 + 1) & 15);
            const float f = tb.x;
            float* __restrict__ p = base + (size_t)ni * (CIN_ * NO_);

            #pragma unroll
            for (int s = 0; s < 8; ++s) {
                const float w0 = __shfl_sync(0xffffffffu, tap[s], s0);
                const float w1 = __shfl_sync(0xffffffffu, tap[s], s1);
                p[s * 256] = w0 + f * (w1 - w0);
            }
        }
    } else {
        // ============== Part 2: rotated bilinear resample (tiny) ==============
        int tid = (blockIdx.x - LERP_BLOCKS) * 256 + threadIdx.x;

        int kx = tid % KS_;
        int ky = (tid / KS_) % KS_;
        int no = (tid / (KS_ * KS_)) & (NO_ - 1);
        int o  = tid / (NO_ * KS_ * KS_);

        float ca, sa;
        sincosf(-out_H[no], &sa, &ca);    // angle = -out_H[no]

        float gx = grid_Rn[(ky * KS_ + kx) * 2 + 0];
        float gy = grid_Rn[(ky * KS_ + kx) * 2 + 1];

        float xr = ca * gx - sa * gy;
        float yr = sa * gx + ca * gy;

        float x = (xr + 1.0f) * 0.5f * (float)(KS_ - 1);
        float y = (yr + 1.0f) * 0.5f * (float)(KS_ - 1);

        float x0f = floorf(x), y0f = floorf(y);
        float wx = x - x0f,  wy = y - y0f;
        int   x0 = (int)x0f, y0 = (int)y0f;

        const float* img = weight + (size_t)o * (KS_ * KS_);

        float v = (1.0f - wy) * (1.0f - wx) * gather7(img, y0,     x0)
                + (1.0f - wy) * wx          * gather7(img, y0,     x0 + 1)
                + wy          * (1.0f - wx) * gather7(img, y0 + 1, x0)
                + wy          * wx          * gather7(img, y0 + 1, x0 + 1);

        out[OUT1_ELEMS + tid] = mask[ky * KS_ + kx] * v;
    }
}

extern "C" void kernel_launch(void* const* d_in, const int* in_sizes, int n_in,
                              void* d_out, int out_size)
{
    const float* in_H     = (const float*)d_in[0];
    const float* out_H    = (const float*)d_in[1];
    const float* weight_H = (const float*)d_in[2];
    const float* weight   = (const float*)d_in[3];
    /* d_in[4] = grid_H (uniform circular grid, implied by K) */
    const float* grid_Rn  = (const float*)d_in[5];
    const float* mask     = (const float*)d_in[6];

    fused_kernel<<<LERP_BLOCKS + ROT_BLOCKS, 256>>>(
        in_H, out_H, weight_H, weight, grid_Rn, mask, (float*)d_out);
}